// round 10
// baseline (speedup 1.0000x reference)
#include <cuda_runtime.h>
#include <cstdint>

#define HW      65536
#define NPIX    (16 * HW)
#define TPB     192
#define TILE_PX 128
#define NBLK    (NPIX / TILE_PX)   // 8192
#define PITCH   100                // sOut row pitch in floats (conflict-free)

typedef unsigned long long u64;

__device__ __forceinline__ u64 ffma2(u64 a, u64 b, u64 c) {
    u64 d;
    asm("fma.rn.f32x2 %0, %1, %2, %3;" : "=l"(d) : "l"(a), "l"(b), "l"(c));
    return d;
}
__device__ __forceinline__ u64 pack2(float lo, float hi) {
    u64 d;
    asm("mov.b64 %0, {%1, %2};" : "=l"(d) : "f"(lo), "f"(hi));
    return d;
}
__device__ __forceinline__ void unpack2(u64 v, float& lo, float& hi) {
    asm("mov.b64 {%0, %1}, %2;" : "=f"(lo), "=f"(hi) : "l"(v));
}

// ---- dynamic smem layout (float units) ----
// OVERLAY: sWp (u64[64][48], 12288 f as f32) is dead after the conv loop;
// sOut (f32[128][PITCH] = 12800 f) reuses the same region. A __syncthreads()
// separates last weight read from first sOut store.
#define F_OVL   0                          // overlay region: max(12288, 12800) f
#define F_SBP   12800                      // u64 [48] conv bias pairs   (96 f)
#define F_SD1P  12896                      // u64 [32][8]                (512 f)
#define F_SD2P  13408                      // u64 [16][4]                (128 f)
#define F_SD3P  13536                      // u64 [8][8]                 (128 f)
#define F_SB3   13664                      // f32 [16]
#define F_SSCL  13680
#define F_TOTAL 13684
#define SMEM_BYTES (F_TOTAL * 4)           // 54,736 B -> 3 CTAs/SM

__global__ void __launch_bounds__(TPB, 3)
fused_ovl_kernel(
    const float* __restrict__ kv_in, const float* __restrict__ q_in,
    const float* __restrict__ key_w, const float* __restrict__ key_b,
    const float* __restrict__ value_w, const float* __restrict__ value_b,
    const float* __restrict__ query_w, const float* __restrict__ query_b,
    const float* __restrict__ scale_p,
    const float* __restrict__ d1_w, const float* __restrict__ d2_w,
    const float* __restrict__ d3_w, const float* __restrict__ d3_b,
    float* __restrict__ out)
{
    extern __shared__ __align__(16) float sm[];
    u64*   sWp  = reinterpret_cast<u64*>(sm + F_OVL);   // [c*48 + pair] (conv phase)
    float* sOut = sm + F_OVL;                           // [px*PITCH + o] (epi phase)
    u64*   sBp  = reinterpret_cast<u64*>(sm + F_SBP);
    u64*   sD1p = reinterpret_cast<u64*>(sm + F_SD1P);
    u64*   sD2p = reinterpret_cast<u64*>(sm + F_SD2P);
    u64*   sD3p = reinterpret_cast<u64*>(sm + F_SD3P);
    float* sB3  = sm + F_SB3;
    float* sScl = sm + F_SSCL;

    const int tid  = threadIdx.x;
    const int wid  = tid >> 5;     // 0..5
    const int lane = tid & 31;
    const int px0  = lane * 4;

    // ---- stage conv weights as out-pairs {w_2p, w_2p+1} ----
    for (int i = tid; i < 64 * 48; i += TPB) {
        int c = i / 48, p = i % 48;
        int o0 = 2 * p, o1 = 2 * p + 1;
        float w0 = (o0 < 32) ? key_w[o0 * 64 + c]
                 : (o0 < 64) ? value_w[(o0 - 32) * 64 + c]
                             : query_w[(o0 - 64) * 64 + c];
        float w1 = (o1 < 32) ? key_w[o1 * 64 + c]
                 : (o1 < 64) ? value_w[(o1 - 32) * 64 + c]
                             : query_w[(o1 - 64) * 64 + c];
        sWp[c * 48 + p] = pack2(w0, w1);
    }
    if (tid < 48) {
        int o0 = 2 * tid, o1 = o0 + 1;
        float b0 = (o0 < 32) ? key_b[o0] : (o0 < 64) ? value_b[o0 - 32] : query_b[o0 - 64];
        float b1 = (o1 < 32) ? key_b[o1] : (o1 < 64) ? value_b[o1 - 32] : query_b[o1 - 64];
        sBp[tid] = pack2(b0, b1);
    }
    for (int i = tid; i < 32 * 8; i += TPB) {
        int c = i >> 3, j = i & 7;
        sD1p[c * 8 + j] = pack2(d1_w[(2 * j) * 32 + c], d1_w[(2 * j + 1) * 32 + c]);
    }
    if (tid < 64) {
        int c = tid >> 2, j = tid & 3;
        sD2p[c * 4 + j] = pack2(d2_w[(2 * j) * 16 + c], d2_w[(2 * j + 1) * 16 + c]);
    }
    if (tid >= 64 && tid < 128) {
        int i = tid - 64;
        int c = i >> 3, j = i & 7;
        sD3p[c * 8 + j] = pack2(d3_w[(2 * j) * 8 + c], d3_w[(2 * j + 1) * 8 + c]);
    }
    if (tid < 16) sB3[tid] = d3_b[tid];
    if (tid == 0) sScl[0] = scale_p[0];
    __syncthreads();

    const int p0   = blockIdx.x * TILE_PX;
    const int b    = p0 >> 16;
    const int poff = p0 & (HW - 1);

    // ---- conv: warp w -> 16 outs (8 pairs); thread: 4 px x 8 out-pairs ----
    const int pbase = (wid < 4) ? wid * 8 : 32 + (wid - 4) * 8;
    const float* src = ((wid < 4) ? kv_in : q_in)
                     + (size_t)b * 64 * HW + poff + px0;

    u64 acc[4][8];
    #pragma unroll
    for (int j = 0; j < 8; ++j) {
        u64 bj = sBp[pbase + j];
        acc[0][j] = bj; acc[1][j] = bj; acc[2][j] = bj; acc[3][j] = bj;
    }

    const u64* wb = sWp + pbase;
    #pragma unroll 4
    for (int c = 0; c < 64; ++c) {
        float4 a = __ldg(reinterpret_cast<const float4*>(src + (size_t)c * HW));
        u64 a0 = pack2(a.x, a.x);
        u64 a1 = pack2(a.y, a.y);
        u64 a2 = pack2(a.z, a.z);
        u64 a3 = pack2(a.w, a.w);
        const ulonglong2* wp = reinterpret_cast<const ulonglong2*>(wb + c * 48);
        #pragma unroll
        for (int j = 0; j < 4; ++j) {
            ulonglong2 w = wp[j];
            acc[0][2*j]   = ffma2(a0, w.x, acc[0][2*j]);
            acc[1][2*j]   = ffma2(a1, w.x, acc[1][2*j]);
            acc[2][2*j]   = ffma2(a2, w.x, acc[2][2*j]);
            acc[3][2*j]   = ffma2(a3, w.x, acc[3][2*j]);
            acc[0][2*j+1] = ffma2(a0, w.y, acc[0][2*j+1]);
            acc[1][2*j+1] = ffma2(a1, w.y, acc[1][2*j+1]);
            acc[2][2*j+1] = ffma2(a2, w.y, acc[2][2*j+1]);
            acc[3][2*j+1] = ffma2(a3, w.y, acc[3][2*j+1]);
        }
    }

    // all warps done reading sWp before sOut overwrites it
    __syncthreads();

    // ---- redistribute: sOut[px][out], 4 STS.128 per px ----
    #pragma unroll
    for (int px = 0; px < 4; ++px) {
        u64* row = reinterpret_cast<u64*>(sOut + (px0 + px) * PITCH) + pbase;
        ulonglong2* r2 = reinterpret_cast<ulonglong2*>(row);
        #pragma unroll
        for (int j = 0; j < 4; ++j) {
            ulonglong2 v;
            v.x = acc[px][2*j];
            v.y = acc[px][2*j+1];
            r2[j] = v;
        }
    }
    __syncthreads();

    // ---- epilogue: threads 0..127, one pixel each ----
    if (tid < TILE_PX) {
        const int px = tid;
        const float scl = sScl[0];
        const float* row = sOut + px * PITCH;

        float x[32];
        #pragma unroll
        for (int o = 0; o < 32; o += 4) {
            float4 kk = *reinterpret_cast<const float4*>(row + o);
            float4 vv = *reinterpret_cast<const float4*>(row + 32 + o);
            float4 qq = *reinterpret_cast<const float4*>(row + 64 + o);
            float z0 = kk.x * qq.x * scl;
            float z1 = kk.y * qq.y * scl;
            float z2 = kk.z * qq.z * scl;
            float z3 = kk.w * qq.w * scl;
            x[o+0] = vv.x * __fdividef(1.0f, 1.0f + __expf(-z0));
            x[o+1] = vv.y * __fdividef(1.0f, 1.0f + __expf(-z1));
            x[o+2] = vv.z * __fdividef(1.0f, 1.0f + __expf(-z2));
            x[o+3] = vv.w * __fdividef(1.0f, 1.0f + __expf(-z3));
        }

        u64 h1p[8];
        #pragma unroll
        for (int j = 0; j < 8; ++j) h1p[j] = 0ull;
        #pragma unroll
        for (int c = 0; c < 32; ++c) {
            u64 xx = pack2(x[c], x[c]);
            const ulonglong2* wr = reinterpret_cast<const ulonglong2*>(&sD1p[c * 8]);
            #pragma unroll
            for (int j = 0; j < 4; ++j) {
                ulonglong2 w = wr[j];
                h1p[2*j]   = ffma2(xx, w.x, h1p[2*j]);
                h1p[2*j+1] = ffma2(xx, w.y, h1p[2*j+1]);
            }
        }
        float h1[16];
        #pragma unroll
        for (int j = 0; j < 8; ++j) {
            float lo, hi; unpack2(h1p[j], lo, hi);
            h1[2*j]   = fmaxf(lo, 0.0f);
            h1[2*j+1] = fmaxf(hi, 0.0f);
        }

        u64 h2p[4];
        #pragma unroll
        for (int j = 0; j < 4; ++j) h2p[j] = 0ull;
        #pragma unroll
        for (int c = 0; c < 16; ++c) {
            u64 xx = pack2(h1[c], h1[c]);
            const ulonglong2* wr = reinterpret_cast<const ulonglong2*>(&sD2p[c * 4]);
            #pragma unroll
            for (int j = 0; j < 2; ++j) {
                ulonglong2 w = wr[j];
                h2p[2*j]   = ffma2(xx, w.x, h2p[2*j]);
                h2p[2*j+1] = ffma2(xx, w.y, h2p[2*j+1]);
            }
        }
        float h2[8];
        #pragma unroll
        for (int j = 0; j < 4; ++j) {
            float lo, hi; unpack2(h2p[j], lo, hi);
            h2[2*j]   = fmaxf(lo, 0.0f);
            h2[2*j+1] = fmaxf(hi, 0.0f);
        }

        u64 o16p[8];
        {
            const u64* b3p = reinterpret_cast<const u64*>(sB3);
            #pragma unroll
            for (int j = 0; j < 8; ++j) o16p[j] = b3p[j];
        }
        #pragma unroll
        for (int c = 0; c < 8; ++c) {
            u64 xx = pack2(h2[c], h2[c]);
            const ulonglong2* wr = reinterpret_cast<const ulonglong2*>(&sD3p[c * 8]);
            #pragma unroll
            for (int j = 0; j < 4; ++j) {
                ulonglong2 w = wr[j];
                o16p[2*j]   = ffma2(xx, w.x, o16p[2*j]);
                o16p[2*j+1] = ffma2(xx, w.y, o16p[2*j+1]);
            }
        }

        float* op = out + ((size_t)b * 16) * HW + poff + px;
        #pragma unroll
        for (int j = 0; j < 8; ++j) {
            float lo, hi; unpack2(o16p[j], lo, hi);
            op[(size_t)(2*j) * HW]   = lo;
            op[(size_t)(2*j+1) * HW] = hi;
        }
    }
}

extern "C" void kernel_launch(void* const* d_in, const int* in_sizes, int n_in,
                              void* d_out, int out_size)
{
    cudaFuncSetAttribute(fused_ovl_kernel,
                         cudaFuncAttributeMaxDynamicSharedMemorySize, SMEM_BYTES);
    fused_ovl_kernel<<<NBLK, TPB, SMEM_BYTES>>>(
        (const float*)d_in[0], (const float*)d_in[1],
        (const float*)d_in[2], (const float*)d_in[3],
        (const float*)d_in[4], (const float*)d_in[5],
        (const float*)d_in[6], (const float*)d_in[7],
        (const float*)d_in[8],
        (const float*)d_in[9], (const float*)d_in[10],
        (const float*)d_in[11], (const float*)d_in[12],
        (float*)d_out);
}

// round 11
// speedup vs baseline: 1.3102x; 1.3102x over previous
#include <cuda_runtime.h>
#include <cstdint>

#define HW      65536
#define NPIX    (16 * HW)
#define TPB     192
#define TILE_PX 128
#define NBLK    (NPIX / TILE_PX)   // 8192
#define PITCH   100                // sOut row pitch in floats

typedef unsigned long long u64;

__device__ __forceinline__ u64 ffma2(u64 a, u64 b, u64 c) {
    u64 d;
    asm("fma.rn.f32x2 %0, %1, %2, %3;" : "=l"(d) : "l"(a), "l"(b), "l"(c));
    return d;
}
__device__ __forceinline__ u64 pack2(float lo, float hi) {
    u64 d;
    asm("mov.b64 %0, {%1, %2};" : "=l"(d) : "f"(lo), "f"(hi));
    return d;
}
__device__ __forceinline__ void unpack2(u64 v, float& lo, float& hi) {
    asm("mov.b64 {%0, %1}, %2;" : "=f"(lo), "=f"(hi) : "l"(v));
}

// ---- dynamic smem layout (float units) ---- (same as R8 best)
#define F_SWP   0                          // u64 [64][48] out-pair conv weights
#define F_SOUT  6144                       // f32 [128][PITCH]
#define F_SBP   18944                      // u64 [48]
#define F_SD1P  19040                      // u64 [32][8]
#define F_SD2P  19552                      // u64 [16][4]
#define F_SD3P  19680                      // u64 [8][8]
#define F_SB3   19808                      // f32 [16]
#define F_SSCL  19824
#define F_TOTAL 19828
#define SMEM_BYTES (F_TOTAL * 4)           // 79,312 B -> 2 CTAs/SM

__global__ void __launch_bounds__(TPB, 2)
fused_o32_kernel(
    const float* __restrict__ kv_in, const float* __restrict__ q_in,
    const float* __restrict__ key_w, const float* __restrict__ key_b,
    const float* __restrict__ value_w, const float* __restrict__ value_b,
    const float* __restrict__ query_w, const float* __restrict__ query_b,
    const float* __restrict__ scale_p,
    const float* __restrict__ d1_w, const float* __restrict__ d2_w,
    const float* __restrict__ d3_w, const float* __restrict__ d3_b,
    float* __restrict__ out)
{
    extern __shared__ __align__(16) float sm[];
    u64*   sWp  = reinterpret_cast<u64*>(sm + F_SWP);   // [c*48 + pair]
    float* sOut = sm + F_SOUT;                          // [px*PITCH + out]
    u64*   sBp  = reinterpret_cast<u64*>(sm + F_SBP);
    u64*   sD1p = reinterpret_cast<u64*>(sm + F_SD1P);
    u64*   sD2p = reinterpret_cast<u64*>(sm + F_SD2P);
    u64*   sD3p = reinterpret_cast<u64*>(sm + F_SD3P);
    float* sB3  = sm + F_SB3;
    float* sScl = sm + F_SSCL;

    const int tid  = threadIdx.x;
    const int wid  = tid >> 5;     // 0..5
    const int lane = tid & 31;

    // ---- stage conv weights as out-pairs {w_2p, w_2p+1} ----
    for (int i = tid; i < 64 * 48; i += TPB) {
        int c = i / 48, p = i % 48;
        int o0 = 2 * p, o1 = 2 * p + 1;
        float w0 = (o0 < 32) ? key_w[o0 * 64 + c]
                 : (o0 < 64) ? value_w[(o0 - 32) * 64 + c]
                             : query_w[(o0 - 64) * 64 + c];
        float w1 = (o1 < 32) ? key_w[o1 * 64 + c]
                 : (o1 < 64) ? value_w[(o1 - 32) * 64 + c]
                             : query_w[(o1 - 64) * 64 + c];
        sWp[c * 48 + p] = pack2(w0, w1);
    }
    if (tid < 48) {
        int o0 = 2 * tid, o1 = o0 + 1;
        float b0 = (o0 < 32) ? key_b[o0] : (o0 < 64) ? value_b[o0 - 32] : query_b[o0 - 64];
        float b1 = (o1 < 32) ? key_b[o1] : (o1 < 64) ? value_b[o1 - 32] : query_b[o1 - 64];
        sBp[tid] = pack2(b0, b1);
    }
    for (int i = tid; i < 32 * 8; i += TPB) {
        int c = i >> 3, j = i & 7;
        sD1p[c * 8 + j] = pack2(d1_w[(2 * j) * 32 + c], d1_w[(2 * j + 1) * 32 + c]);
    }
    if (tid < 64) {
        int c = tid >> 2, j = tid & 3;
        sD2p[c * 4 + j] = pack2(d2_w[(2 * j) * 16 + c], d2_w[(2 * j + 1) * 16 + c]);
    }
    if (tid >= 64 && tid < 128) {
        int i = tid - 64;
        int c = i >> 3, j = i & 7;
        sD3p[c * 8 + j] = pack2(d3_w[(2 * j) * 8 + c], d3_w[(2 * j + 1) * 8 + c]);
    }
    if (tid < 16) sB3[tid] = d3_b[tid];
    if (tid == 0) sScl[0] = scale_p[0];
    __syncthreads();

    const int p0   = blockIdx.x * TILE_PX;
    const int b    = p0 >> 16;
    const int poff = p0 & (HW - 1);

    // ---- conv blocking: R_px=2, R_out=32 (16 pairs) ----
    // kv: wid 0..3 -> out-group og=wid>>1 (pairs 16*og..16*og+16),
    //                 px-range pr=wid&1 (px 64*pr + lane*2)
    // q : wid 4..5 -> pairs 32..48, px-range pr=wid-4
    const int is_q  = (wid >= 4);
    const int og    = is_q ? 2 : (wid >> 1);
    const int pr    = is_q ? (wid - 4) : (wid & 1);
    const int pbase = og * 16;                 // pair index base
    const int px0   = pr * 64 + lane * 2;

    const float* src = (is_q ? q_in : kv_in)
                     + (size_t)b * 64 * HW + poff + px0;

    u64 acc0[16], acc1[16];    // px0, px0+1
    #pragma unroll
    for (int j = 0; j < 16; ++j) {
        u64 bj = sBp[pbase + j];
        acc0[j] = bj;
        acc1[j] = bj;
    }

    const u64* wb = sWp + pbase;
    #pragma unroll 8
    for (int c = 0; c < 64; ++c) {
        float2 a = __ldg(reinterpret_cast<const float2*>(src + (size_t)c * HW));
        u64 a0 = pack2(a.x, a.x);
        u64 a1 = pack2(a.y, a.y);
        const ulonglong2* wp = reinterpret_cast<const ulonglong2*>(wb + c * 48);
        #pragma unroll
        for (int j = 0; j < 8; ++j) {
            ulonglong2 w = wp[j];
            acc0[2*j]   = ffma2(a0, w.x, acc0[2*j]);
            acc1[2*j]   = ffma2(a1, w.x, acc1[2*j]);
            acc0[2*j+1] = ffma2(a0, w.y, acc0[2*j+1]);
            acc1[2*j+1] = ffma2(a1, w.y, acc1[2*j+1]);
        }
    }

    // ---- redistribute: sOut[px][out], 8 STS.128 per px ----
    {
        ulonglong2* r0 = reinterpret_cast<ulonglong2*>(
            reinterpret_cast<u64*>(sOut + px0 * PITCH) + pbase);
        ulonglong2* r1 = reinterpret_cast<ulonglong2*>(
            reinterpret_cast<u64*>(sOut + (px0 + 1) * PITCH) + pbase);
        #pragma unroll
        for (int j = 0; j < 8; ++j) {
            ulonglong2 v0, v1;
            v0.x = acc0[2*j]; v0.y = acc0[2*j+1];
            v1.x = acc1[2*j]; v1.y = acc1[2*j+1];
            r0[j] = v0;
            r1[j] = v1;
        }
    }
    __syncthreads();

    // ---- epilogue: threads 0..127, one pixel each ----
    if (tid < TILE_PX) {
        const int px = tid;
        const float scl = sScl[0];
        const float* row = sOut + px * PITCH;

        float x[32];
        #pragma unroll
        for (int o = 0; o < 32; o += 4) {
            float4 kk = *reinterpret_cast<const float4*>(row + o);
            float4 vv = *reinterpret_cast<const float4*>(row + 32 + o);
            float4 qq = *reinterpret_cast<const float4*>(row + 64 + o);
            float z0 = kk.x * qq.x * scl;
            float z1 = kk.y * qq.y * scl;
            float z2 = kk.z * qq.z * scl;
            float z3 = kk.w * qq.w * scl;
            x[o+0] = vv.x * __fdividef(1.0f, 1.0f + __expf(-z0));
            x[o+1] = vv.y * __fdividef(1.0f, 1.0f + __expf(-z1));
            x[o+2] = vv.z * __fdividef(1.0f, 1.0f + __expf(-z2));
            x[o+3] = vv.w * __fdividef(1.0f, 1.0f + __expf(-z3));
        }

        u64 h1p[8];
        #pragma unroll
        for (int j = 0; j < 8; ++j) h1p[j] = 0ull;
        #pragma unroll
        for (int c = 0; c < 32; ++c) {
            u64 xx = pack2(x[c], x[c]);
            const ulonglong2* wr = reinterpret_cast<const ulonglong2*>(&sD1p[c * 8]);
            #pragma unroll
            for (int j = 0; j < 4; ++j) {
                ulonglong2 w = wr[j];
                h1p[2*j]   = ffma2(xx, w.x, h1p[2*j]);
                h1p[2*j+1] = ffma2(xx, w.y, h1p[2*j+1]);
            }
        }
        float h1[16];
        #pragma unroll
        for (int j = 0; j < 8; ++j) {
            float lo, hi; unpack2(h1p[j], lo, hi);
            h1[2*j]   = fmaxf(lo, 0.0f);
            h1[2*j+1] = fmaxf(hi, 0.0f);
        }

        u64 h2p[4];
        #pragma unroll
        for (int j = 0; j < 4; ++j) h2p[j] = 0ull;
        #pragma unroll
        for (int c = 0; c < 16; ++c) {
            u64 xx = pack2(h1[c], h1[c]);
            const ulonglong2* wr = reinterpret_cast<const ulonglong2*>(&sD2p[c * 4]);
            #pragma unroll
            for (int j = 0; j < 2; ++j) {
                ulonglong2 w = wr[j];
                h2p[2*j]   = ffma2(xx, w.x, h2p[2*j]);
                h2p[2*j+1] = ffma2(xx, w.y, h2p[2*j+1]);
            }
        }
        float h2[8];
        #pragma unroll
        for (int j = 0; j < 4; ++j) {
            float lo, hi; unpack2(h2p[j], lo, hi);
            h2[2*j]   = fmaxf(lo, 0.0f);
            h2[2*j+1] = fmaxf(hi, 0.0f);
        }

        u64 o16p[8];
        {
            const u64* b3p = reinterpret_cast<const u64*>(sB3);
            #pragma unroll
            for (int j = 0; j < 8; ++j) o16p[j] = b3p[j];
        }
        #pragma unroll
        for (int c = 0; c < 8; ++c) {
            u64 xx = pack2(h2[c], h2[c]);
            const ulonglong2* wr = reinterpret_cast<const ulonglong2*>(&sD3p[c * 8]);
            #pragma unroll
            for (int j = 0; j < 4; ++j) {
                ulonglong2 w = wr[j];
                o16p[2*j]   = ffma2(xx, w.x, o16p[2*j]);
                o16p[2*j+1] = ffma2(xx, w.y, o16p[2*j+1]);
            }
        }

        float* op = out + ((size_t)b * 16) * HW + poff + px;
        #pragma unroll
        for (int j = 0; j < 8; ++j) {
            float lo, hi; unpack2(o16p[j], lo, hi);
            op[(size_t)(2*j) * HW]   = lo;
            op[(size_t)(2*j+1) * HW] = hi;
        }
    }
}

extern "C" void kernel_launch(void* const* d_in, const int* in_sizes, int n_in,
                              void* d_out, int out_size)
{
    cudaFuncSetAttribute(fused_o32_kernel,
                         cudaFuncAttributeMaxDynamicSharedMemorySize, SMEM_BYTES);
    fused_o32_kernel<<<NBLK, TPB, SMEM_BYTES>>>(
        (const float*)d_in[0], (const float*)d_in[1],
        (const float*)d_in[2], (const float*)d_in[3],
        (const float*)d_in[4], (const float*)d_in[5],
        (const float*)d_in[6], (const float*)d_in[7],
        (const float*)d_in[8],
        (const float*)d_in[9], (const float*)d_in[10],
        (const float*)d_in[11], (const float*)d_in[12],
        (float*)d_out);
}

// round 13
// speedup vs baseline: 2.4758x; 1.8896x over previous
#include <cuda_runtime.h>
#include <cuda_bf16.h>
#include <cstdint>

#define HW      65536
#define TPB     256
#define TILE_PX 128
#define NBLK    8192
#define PITCHX  36           // sX row pitch (floats): 144B rows, conflict-free float4

typedef unsigned long long u64;
typedef uint32_t u32;

__device__ __forceinline__ u64 ffma2(u64 a, u64 b, u64 c) {
    u64 d;
    asm("fma.rn.f32x2 %0, %1, %2, %3;" : "=l"(d) : "l"(a), "l"(b), "l"(c));
    return d;
}
__device__ __forceinline__ u64 packf2(float lo, float hi) {
    u64 d;
    asm("mov.b64 %0, {%1, %2};" : "=l"(d) : "f"(lo), "f"(hi));
    return d;
}
__device__ __forceinline__ void unpackf2(u64 v, float& lo, float& hi) {
    asm("mov.b64 {%0, %1}, %2;" : "=f"(lo), "=f"(hi) : "l"(v));
}

// bf16 hi/lo split of fp32
__device__ __forceinline__ void bsplit(float a, uint16_t& h, uint16_t& l) {
    __nv_bfloat16 hb = __float2bfloat16_rn(a);
    h = __bfloat16_as_ushort(hb);
    float r = a - __bfloat162float(hb);
    l = __bfloat16_as_ushort(__float2bfloat16_rn(r));
}

// m16n8k16 row.col f32.bf16.bf16.f32, in-place accumulate
__device__ __forceinline__ void mma16816(float* c, u32 a0, u32 a1, u32 a2, u32 a3,
                                         u32 b0, u32 b1) {
    asm volatile(
        "mma.sync.aligned.m16n8k16.row.col.f32.bf16.bf16.f32 "
        "{%0,%1,%2,%3}, {%4,%5,%6,%7}, {%8,%9}, {%0,%1,%2,%3};"
        : "+f"(c[0]), "+f"(c[1]), "+f"(c[2]), "+f"(c[3])
        : "r"(a0), "r"(a1), "r"(a2), "r"(a3), "r"(b0), "r"(b1));
}

__global__ void __launch_bounds__(TPB, 2)
fused_mma_kernel(
    const float* __restrict__ kv_in, const float* __restrict__ q_in,
    const float* __restrict__ key_w, const float* __restrict__ key_b,
    const float* __restrict__ value_w, const float* __restrict__ value_b,
    const float* __restrict__ query_w, const float* __restrict__ query_b,
    const float* __restrict__ scale_p,
    const float* __restrict__ d1_w, const float* __restrict__ d2_w,
    const float* __restrict__ d3_w, const float* __restrict__ d3_b,
    float* __restrict__ out)
{
    // B fragment tables in exact mma fragment order: [s][j][lane] -> {b0,b1}
    __shared__ u64 sBH[4 * 12 * 32];    // 12 KB  (hi parts)
    __shared__ u64 sBL[4 * 12 * 32];    // 12 KB  (lo parts)
    __shared__ u64 sBiasP[48];          // conv bias pairs (k|v|q)
    __shared__ u64 sD1p[32 * 8];
    __shared__ u64 sD2p[16 * 4];
    __shared__ u64 sD3p[8 * 8];
    __shared__ float sB3[16];
    __shared__ float sScl;
    __shared__ __align__(16) float sX[TILE_PX * PITCHX];   // 18 KB

    const int tid  = threadIdx.x;
    const int lane = tid & 31;
    const int wrp  = tid >> 5;      // 0..7
    const int gid  = lane >> 2;     // 0..7
    const int tig  = lane & 3;      // 0..3

    // ---- stage B fragment tables (once) ----
    // B[k][n]: n<32 key_w[n][k]; n<64 value_w[n-32][k]; else query_w[n-64][k]
    for (int i = tid; i < 4 * 12 * 32; i += TPB) {
        int l = i & 31, j = (i >> 5) % 12, s = i / (12 * 32);
        int n = j * 8 + (l >> 2);
        int k0 = s * 16 + 2 * (l & 3);
        const float* wrow = (n < 32) ? (key_w + n * 64)
                          : (n < 64) ? (value_w + (n - 32) * 64)
                                     : (query_w + (n - 64) * 64);
        float w00 = wrow[k0],     w01 = wrow[k0 + 1];
        float w10 = wrow[k0 + 8], w11 = wrow[k0 + 9];
        uint16_t h00, l00, h01, l01, h10, l10, h11, l11;
        bsplit(w00, h00, l00); bsplit(w01, h01, l01);
        bsplit(w10, h10, l10); bsplit(w11, h11, l11);
        u32 bh0 = (u32)h00 | ((u32)h01 << 16);
        u32 bh1 = (u32)h10 | ((u32)h11 << 16);
        u32 bl0 = (u32)l00 | ((u32)l01 << 16);
        u32 bl1 = (u32)l10 | ((u32)l11 << 16);
        sBH[i] = ((u64)bh1 << 32) | bh0;
        sBL[i] = ((u64)bl1 << 32) | bl0;
    }
    if (tid < 48) {
        int o0 = 2 * tid, o1 = o0 + 1;
        float b0 = (o0 < 32) ? key_b[o0] : (o0 < 64) ? value_b[o0 - 32] : query_b[o0 - 64];
        float b1 = (o1 < 32) ? key_b[o1] : (o1 < 64) ? value_b[o1 - 32] : query_b[o1 - 64];
        sBiasP[tid] = packf2(b0, b1);
    }
    for (int i = tid; i < 32 * 8; i += TPB) {
        int c = i >> 3, j = i & 7;
        sD1p[c * 8 + j] = packf2(d1_w[(2 * j) * 32 + c], d1_w[(2 * j + 1) * 32 + c]);
    }
    if (tid < 64) {
        int c = tid >> 2, j = tid & 3;
        sD2p[c * 4 + j] = packf2(d2_w[(2 * j) * 16 + c], d2_w[(2 * j + 1) * 16 + c]);
    }
    if (tid >= 64 && tid < 128) {
        int i = tid - 64;
        int c = i >> 3, j = i & 7;
        sD3p[c * 8 + j] = packf2(d3_w[(2 * j) * 8 + c], d3_w[(2 * j + 1) * 8 + c]);
    }
    if (tid < 16) sB3[tid] = d3_b[tid];
    if (tid == 0) sScl = scale_p[0];
    __syncthreads();

    const int p0   = blockIdx.x * TILE_PX;
    const int b    = p0 >> 16;
    const int poff = p0 & (HW - 1);
    const float* kvb = kv_in + (size_t)b * 64 * HW + poff;
    const float* qb  = q_in  + (size_t)b * 64 * HW + poff;

    const int pxr = 16 * wrp + gid;     // tile-local row, rr=0

    float acc[12][4];
    #pragma unroll
    for (int j = 0; j < 12; ++j)
        #pragma unroll
        for (int e = 0; e < 4; ++e) acc[j][e] = 0.0f;

    // ---- main GEMM: 4 k-steps, 3-pass bf16 hi/lo ----
    #pragma unroll
    for (int s = 0; s < 4; ++s) {
        // A fragments direct from global (standard m16k16 row-major thread map):
        // reg i = rr + 2*cc; element e: A[pxr + 8*rr][s*16 + 2*tig + e + 8*cc]
        float avk[8], avq[8];
        #pragma unroll
        for (int cc = 0; cc < 2; ++cc)
            #pragma unroll
            for (int rr = 0; rr < 2; ++rr)
                #pragma unroll
                for (int e = 0; e < 2; ++e) {
                    int c  = s * 16 + 2 * tig + e + 8 * cc;
                    int px = pxr + 8 * rr;
                    int i  = (rr + 2 * cc) * 2 + e;
                    avk[i] = __ldg(kvb + (size_t)c * HW + px);
                    avq[i] = __ldg(qb  + (size_t)c * HW + px);
                }
        u32 akh[4], akl[4], aqh[4], aql[4];
        #pragma unroll
        for (int i = 0; i < 4; ++i) {
            uint16_t h0, l0, h1, l1;
            bsplit(avk[2 * i], h0, l0); bsplit(avk[2 * i + 1], h1, l1);
            akh[i] = (u32)h0 | ((u32)h1 << 16);
            akl[i] = (u32)l0 | ((u32)l1 << 16);
            bsplit(avq[2 * i], h0, l0); bsplit(avq[2 * i + 1], h1, l1);
            aqh[i] = (u32)h0 | ((u32)h1 << 16);
            aql[i] = (u32)l0 | ((u32)l1 << 16);
        }

        const int base = s * 384 + lane;
        #pragma unroll
        for (int j = 0; j < 8; ++j) {            // kv: n-tiles 0..7
            u64 vh = sBH[base + j * 32];
            u64 vl = sBL[base + j * 32];
            u32 bh0 = (u32)vh, bh1 = (u32)(vh >> 32);
            u32 bl0 = (u32)vl, bl1 = (u32)(vl >> 32);
            mma16816(acc[j], akh[0], akh[1], akh[2], akh[3], bh0, bh1);
            mma16816(acc[j], akh[0], akh[1], akh[2], akh[3], bl0, bl1);
            mma16816(acc[j], akl[0], akl[1], akl[2], akl[3], bh0, bh1);
        }
        #pragma unroll
        for (int j = 8; j < 12; ++j) {           // q: n-tiles 8..11
            u64 vh = sBH[base + j * 32];
            u64 vl = sBL[base + j * 32];
            u32 bh0 = (u32)vh, bh1 = (u32)(vh >> 32);
            u32 bl0 = (u32)vl, bl1 = (u32)(vl >> 32);
            mma16816(acc[j], aqh[0], aqh[1], aqh[2], aqh[3], bh0, bh1);
            mma16816(acc[j], aqh[0], aqh[1], aqh[2], aqh[3], bl0, bl1);
            mma16816(acc[j], aql[0], aql[1], aql[2], aql[3], bh0, bh1);
        }
    }

    // ---- gate in registers; x -> sX ----
    {
        const float scl = sScl;
        #pragma unroll
        for (int j = 0; j < 4; ++j) {
            float bk0, bk1, bv0, bv1, bq0, bq1;
            unpackf2(sBiasP[4 * j + tig],      bk0, bk1);
            unpackf2(sBiasP[16 + 4 * j + tig], bv0, bv1);
            unpackf2(sBiasP[32 + 4 * j + tig], bq0, bq1);
            #pragma unroll
            for (int rr = 0; rr < 2; ++rr) {
                float kk0 = acc[j][2 * rr]     + bk0;
                float kk1 = acc[j][2 * rr + 1] + bk1;
                float vv0 = acc[j + 4][2 * rr]     + bv0;
                float vv1 = acc[j + 4][2 * rr + 1] + bv1;
                float qq0 = acc[j + 8][2 * rr]     + bq0;
                float qq1 = acc[j + 8][2 * rr + 1] + bq1;
                float z0 = kk0 * qq0 * scl;
                float z1 = kk1 * qq1 * scl;
                float x0 = vv0 * __fdividef(1.0f, 1.0f + __expf(-z0));
                float x1 = vv1 * __fdividef(1.0f, 1.0f + __expf(-z1));
                int px = pxr + 8 * rr;
                *reinterpret_cast<float2*>(&sX[px * PITCHX + 8 * j + 2 * tig]) =
                    make_float2(x0, x1);
            }
        }
    }
    __syncthreads();

    // ---- chain: threads 0..127, one pixel each (R8 epilogue) ----
    if (tid < TILE_PX) {
        const int px = tid;
        const float* row = sX + px * PITCHX;

        float x[32];
        #pragma unroll
        for (int o = 0; o < 32; o += 4) {
            float4 v4 = *reinterpret_cast<const float4*>(row + o);
            x[o] = v4.x; x[o+1] = v4.y; x[o+2] = v4.z; x[o+3] = v4.w;
        }

        u64 h1p[8];
        #pragma unroll
        for (int j = 0; j < 8; ++j) h1p[j] = 0ull;
        #pragma unroll
        for (int c = 0; c < 32; ++c) {
            u64 xx = packf2(x[c], x[c]);
            const ulonglong2* wr = reinterpret_cast<const ulonglong2*>(&sD1p[c * 8]);
            #pragma unroll
            for (int j = 0; j < 4; ++j) {
                ulonglong2 w = wr[j];
                h1p[2*j]   = ffma2(xx, w.x, h1p[2*j]);
                h1p[2*j+1] = ffma2(xx, w.y, h1p[2*j+1]);
            }
        }
        float h1[16];
        #pragma unroll
        for (int j = 0; j < 8; ++j) {
            float lo, hi; unpackf2(h1p[j], lo, hi);
            h1[2*j]   = fmaxf(lo, 0.0f);
            h1[2*j+1] = fmaxf(hi, 0.0f);
        }

        u64 h2p[4];
        #pragma unroll
        for (int j = 0; j < 4; ++j) h2p[j] = 0ull;
        #pragma unroll
        for (int c = 0; c < 16; ++c) {
            u64 xx = packf2(h1[c], h1[c]);
            const ulonglong2* wr = reinterpret_cast<const ulonglong2*>(&sD2p[c * 4]);
            #pragma unroll
            for (int j = 0; j < 2; ++j) {
                ulonglong2 w = wr[j];
                h2p[2*j]   = ffma2(xx, w.x, h2p[2*j]);
                h2p[2*j+1] = ffma2(xx, w.y, h2p[2*j+1]);
            }
        }
        float h2[8];
        #pragma unroll
        for (int j = 0; j < 4; ++j) {
            float lo, hi; unpackf2(h2p[j], lo, hi);
            h2[2*j]   = fmaxf(lo, 0.0f);
            h2[2*j+1] = fmaxf(hi, 0.0f);
        }

        u64 o16p[8];
        {
            const u64* b3p = reinterpret_cast<const u64*>(sB3);
            #pragma unroll
            for (int j = 0; j < 8; ++j) o16p[j] = b3p[j];
        }
        #pragma unroll
        for (int c = 0; c < 8; ++c) {
            u64 xx = packf2(h2[c], h2[c]);
            const ulonglong2* wr = reinterpret_cast<const ulonglong2*>(&sD3p[c * 8]);
            #pragma unroll
            for (int j = 0; j < 4; ++j) {
                ulonglong2 w = wr[j];
                o16p[2*j]   = ffma2(xx, w.x, o16p[2*j]);
                o16p[2*j+1] = ffma2(xx, w.y, o16p[2*j+1]);
            }
        }

        float* op = out + ((size_t)b * 16) * HW + poff + px;
        #pragma unroll
        for (int j = 0; j < 8; ++j) {
            float lo, hi; unpackf2(o16p[j], lo, hi);
            op[(size_t)(2*j) * HW]   = lo;
            op[(size_t)(2*j+1) * HW] = hi;
        }
    }
}

extern "C" void kernel_launch(void* const* d_in, const int* in_sizes, int n_in,
                              void* d_out, int out_size)
{
    fused_mma_kernel<<<NBLK, TPB>>>(
        (const float*)d_in[0], (const float*)d_in[1],
        (const float*)d_in[2], (const float*)d_in[3],
        (const float*)d_in[4], (const float*)d_in[5],
        (const float*)d_in[6], (const float*)d_in[7],
        (const float*)d_in[8],
        (const float*)d_in[9], (const float*)d_in[10],
        (const float*)d_in[11], (const float*)d_in[12],
        (float*)d_out);
}